// round 4
// baseline (speedup 1.0000x reference)
#include <cuda_runtime.h>
#include <cstdint>

#define NMAX 100000
#define EMAX 1600000

// ---------------- scratch (device globals, referenced ONLY from device code) -
__device__ int   g_is64;
__device__ float g_dinv [NMAX];
__device__ int   g_cnt  [NMAX];
__device__ int   g_ptr  [NMAX + 1];
__device__ int   g_cur  [NMAX];
__device__ int   g_row  [EMAX];
__device__ int   g_col  [EMAX];
__device__ int   g_srow [EMAX];    // CSR-ordered source row per slot
__device__ float g_sval [EMAX];    // CSR-ordered: edge weight, then norm
__device__ float g_xw1 [NMAX * 64];
__device__ float g_h1  [NMAX * 64];   // tanh(agg1)
__device__ float g_xw2 [NMAX * 32];
__device__ float g_hact[NMAX * 32];   // tanh(emb)
__device__ float g_xw3 [NMAX * 16];

// ---------------- dtype probe: int64 vs int32 edge_index --------------------
// int64 values < 2^31 have zero high words (odd 32-bit words, little-endian).
__global__ void k_detect(const int* __restrict__ ei32) {
    int z = 0;
#pragma unroll
    for (int i = 1; i < 16; i += 2) z |= ei32[i];
    g_is64 = (z == 0) ? 1 : 0;
}

// ---------------- CSR build (no float atomics) ------------------------------
__global__ void k_init(int n) {
    int i = blockIdx.x * blockDim.x + threadIdx.x;
    if (i < n) g_cnt[i] = 0;
}

__device__ __forceinline__ int load_idx(const int* ei, int pos) {
    return g_is64 ? ei[2 * pos] : ei[pos];   // low word if int64
}

__global__ void k_cnt(const int* __restrict__ ei, int E, int N) {
    int e = blockIdx.x * blockDim.x + threadIdx.x;
    if (e < E) {
        int r = load_idx(ei, e);
        int c = load_idx(ei, E + e);
        if ((unsigned)r >= (unsigned)N) r = 0;   // safety clamp
        if ((unsigned)c >= (unsigned)N) c = 0;
        g_row[e] = r;
        g_col[e] = c;
        atomicAdd(&g_cnt[c], 1);
    }
}

__global__ void k_scan(int n) {
    __shared__ int sblk[1024];
    const int T = 1024;
    int chunk = (n + T - 1) / T;
    int t = threadIdx.x;
    int begin = t * chunk;
    int end = begin + chunk; if (end > n) end = n;
    int s = 0;
    for (int i = begin; i < end; i++) s += g_cnt[i];
    sblk[t] = s;
    __syncthreads();
    if (t == 0) {
        int run = 0;
        for (int i = 0; i < T; i++) { int v = sblk[i]; sblk[i] = run; run += v; }
    }
    __syncthreads();
    int run = sblk[t];
    for (int i = begin; i < end; i++) {
        g_ptr[i] = run;
        g_cur[i] = run;
        run += g_cnt[i];
    }
    if (t == T - 1) g_ptr[n] = run;
}

__global__ void k_fill(const float* __restrict__ ew, int E) {
    int e = blockIdx.x * blockDim.x + threadIdx.x;
    if (e >= E) return;
    int pos = atomicAdd(&g_cur[g_col[e]], 1);
    g_srow[pos] = g_row[e];
    g_sval[pos] = ew[e];
}

// deg = 1 (self loop) + sum incoming edge weights; dinv = rsqrt(deg)
__global__ void k_degdinv(int N) {
    int node = (blockIdx.x * blockDim.x + threadIdx.x) >> 5;
    if (node >= N) return;
    int lane = threadIdx.x & 31;
    int beg = g_ptr[node], end = g_ptr[node + 1];
    float s = 0.0f;
    for (int p = beg + lane; p < end; p += 32) s += g_sval[p];
#pragma unroll
    for (int o = 16; o; o >>= 1) s += __shfl_xor_sync(0xffffffffu, s, o);
    if (lane == 0) g_dinv[node] = rsqrtf(1.0f + s);
}

// overwrite stored edge weight with full symmetric norm
__global__ void k_norm(int N) {
    int node = (blockIdx.x * blockDim.x + threadIdx.x) >> 5;
    if (node >= N) return;
    int lane = threadIdx.x & 31;
    int beg = g_ptr[node], end = g_ptr[node + 1];
    float dc = g_dinv[node];
    for (int p = beg + lane; p < end; p += 32)
        g_sval[p] = g_dinv[g_srow[p]] * g_sval[p] * dc;
}

// ---------------- register-tiled fp32 GEMM body -----------------------------
template<int K, int FOUT, int TN>
__device__ __forceinline__ void gemm_body(const float* __restrict__ X,
                                          const float* __restrict__ W,
                                          float* __restrict__ out, int N) {
    constexpr int BM = 64;
    constexpr int TM = 4;
    constexpr int KC = 32;
    __shared__ float sW[K * FOUT];
    __shared__ float sX[BM][KC + 1];

    const int tid = threadIdx.x;
    const int tx  = tid & 15;
    const int ty  = tid >> 4;
    const int row0 = blockIdx.x * BM;

    for (int i = tid; i < K * FOUT; i += 256) sW[i] = W[i];

    float acc[TM][TN];
#pragma unroll
    for (int i = 0; i < TM; i++)
#pragma unroll
        for (int j = 0; j < TN; j++) acc[i][j] = 0.0f;

    for (int k0 = 0; k0 < K; k0 += KC) {
        __syncthreads();
        for (int i = tid; i < BM * KC; i += 256) {
            int r = i / KC, c = i - r * KC;
            int gr = row0 + r;
            sX[r][c] = (gr < N) ? X[(size_t)gr * K + k0 + c] : 0.0f;
        }
        __syncthreads();
#pragma unroll
        for (int k = 0; k < KC; k++) {
            float xr[TM], wr[TN];
#pragma unroll
            for (int i = 0; i < TM; i++) xr[i] = sX[ty + 16 * i][k];
#pragma unroll
            for (int j = 0; j < TN; j++) wr[j] = sW[(k0 + k) * FOUT + tx + 16 * j];
#pragma unroll
            for (int i = 0; i < TM; i++)
#pragma unroll
                for (int j = 0; j < TN; j++)
                    acc[i][j] += xr[i] * wr[j];
        }
    }
#pragma unroll
    for (int i = 0; i < TM; i++) {
        int gr = row0 + ty + 16 * i;
        if (gr < N) {
#pragma unroll
            for (int j = 0; j < TN; j++)
                out[(size_t)gr * FOUT + tx + 16 * j] = acc[i][j];
        }
    }
}

__global__ void k_gemm1(const float* __restrict__ X, const float* __restrict__ W, int N) {
    gemm_body<128, 64, 4>(X, W, g_xw1, N);
}
__global__ void k_gemm2(const float* __restrict__ W, int N) {
    gemm_body<64, 32, 2>(g_h1, W, g_xw2, N);
}
__global__ void k_gemm3(const float* __restrict__ W, int N) {
    gemm_body<32, 16, 1>(g_hact, W, g_xw3, N);
}

// ---------------- CSR gather aggregation, one warp per node -----------------
// out = act(b + dinv^2 * xw[node] + sum_edges norm * xw[src])

__global__ void k_agg1(const float* __restrict__ b, int N) {
    int node = (blockIdx.x * blockDim.x + threadIdx.x) >> 5;
    if (node >= N) return;
    int lane = threadIdx.x & 31;
    int beg = g_ptr[node], end = g_ptr[node + 1];
    float a0 = 0.0f, a1 = 0.0f;
    for (int p = beg; p < end; p++) {
        int r = g_srow[p];
        float nm = g_sval[p];
        const float* src = g_xw1 + (size_t)r * 64;
        a0 += nm * src[lane];
        a1 += nm * src[lane + 32];
    }
    float di = g_dinv[node];
    float d2 = di * di;
    const float* self = g_xw1 + (size_t)node * 64;
    a0 += d2 * self[lane]      + b[lane];
    a1 += d2 * self[lane + 32] + b[lane + 32];
    g_h1[(size_t)node * 64 + lane]      = tanhf(a0);
    g_h1[(size_t)node * 64 + lane + 32] = tanhf(a1);
}

__global__ void k_agg2(const float* __restrict__ b, float* __restrict__ emb, int N) {
    int node = (blockIdx.x * blockDim.x + threadIdx.x) >> 5;
    if (node >= N) return;
    int lane = threadIdx.x & 31;
    int beg = g_ptr[node], end = g_ptr[node + 1];
    float a = 0.0f;
    for (int p = beg; p < end; p++) {
        int r = g_srow[p];
        float nm = g_sval[p];
        a += nm * g_xw2[(size_t)r * 32 + lane];
    }
    float di = g_dinv[node];
    float val = a + di * di * g_xw2[(size_t)node * 32 + lane] + b[lane];
    emb[(size_t)node * 32 + lane] = val;
    g_hact[(size_t)node * 32 + lane] = tanhf(val);
}

__global__ void k_agg3(const float* __restrict__ b, float* __restrict__ logits, int N) {
    int node = (blockIdx.x * blockDim.x + threadIdx.x) >> 5;
    if (node >= N) return;
    int lane = threadIdx.x & 31;
    int sub = lane >> 4;
    int f = lane & 15;
    int beg = g_ptr[node], end = g_ptr[node + 1];
    float a = 0.0f;
    for (int p = beg + sub; p < end; p += 2) {
        int r = g_srow[p];
        float nm = g_sval[p];
        a += nm * g_xw3[(size_t)r * 16 + f];
    }
    a += __shfl_xor_sync(0xffffffffu, a, 16);
    if (sub == 0) {
        float di = g_dinv[node];
        logits[(size_t)node * 16 + f] =
            a + di * di * g_xw3[(size_t)node * 16 + f] + b[f];
    }
}

// ---------------- launch: ONLY kernel launches, no CUDA host APIs -----------
extern "C" void kernel_launch(void* const* d_in, const int* in_sizes, int n_in,
                              void* d_out, int out_size) {
    const float* x  = (const float*)d_in[0];
    const int*   ei = (const int*)d_in[1];     // int32 OR int64 (probed on device)
    const float* ew = (const float*)d_in[2];
    const float* W1 = (const float*)d_in[3];
    const float* b1 = (const float*)d_in[4];
    const float* W2 = (const float*)d_in[5];
    const float* b2 = (const float*)d_in[6];
    const float* W3 = (const float*)d_in[7];
    const float* b3 = (const float*)d_in[8];

    const int N = in_sizes[0] / 128;
    const int E = in_sizes[2];

    float* logits = (float*)d_out;                    // [N,16]
    float* emb    = (float*)d_out + (size_t)N * 16;   // [N,32]

    const int T = 256;
    auto cdiv = [](long long a, long long b) { return (int)((a + b - 1) / b); };
    const int warpGrid = cdiv((long long)N * 32, T);  // one warp per node

    // ---- CSR build (shared by all layers) ----
    k_detect <<<1, 1>>>(ei);
    k_init   <<<cdiv(N, T), T>>>(N);
    k_cnt    <<<cdiv(E, T), T>>>(ei, E, N);
    k_scan   <<<1, 1024>>>(N);
    k_fill   <<<cdiv(E, T), T>>>(ew, E);
    k_degdinv<<<warpGrid, T>>>(N);
    k_norm   <<<warpGrid, T>>>(N);

    // ---- layer 1: h1 = tanh(conv(x, W1, b1)) ----
    k_gemm1<<<cdiv(N, 64), T>>>(x, W1, N);
    k_agg1 <<<warpGrid, T>>>(b1, N);

    // ---- layer 2: emb = conv(h1, W2, b2); hact = tanh(emb) ----
    k_gemm2<<<cdiv(N, 64), T>>>(W2, N);
    k_agg2 <<<warpGrid, T>>>(b2, emb, N);

    // ---- layer 3: logits = conv(hact, W3, b3) ----
    k_gemm3<<<cdiv(N, 64), T>>>(W3, N);
    k_agg3 <<<warpGrid, T>>>(b3, logits, N);
}

// round 6
// speedup vs baseline: 1.4604x; 1.4604x over previous
#include <cuda_runtime.h>
#include <cstdint>

#define NMAX 100000
#define EMAX 1600000
#define SCAN_T 1024
#define MAXBLK 128    // max scan blocks (ceil(NMAX/1024) = 98)

// ---------------- scratch (device globals, device-side references only) -----
__device__ int   g_is64;
__device__ float g_dinv [NMAX];
__device__ int   g_cnt  [NMAX];
__device__ int   g_part [NMAX];      // per-element exclusive scan within block
__device__ int   g_bsum [MAXBLK];    // per-block totals -> scanned in place
__device__ int   g_ptr  [NMAX + 1];
__device__ int   g_cur  [NMAX];
__device__ int   g_row  [EMAX];
__device__ int   g_col  [EMAX];
__device__ int   g_srow [EMAX];      // CSR-ordered source row per slot
__device__ float g_sval [EMAX];      // CSR-ordered: edge weight, then norm
__device__ float g_xw1 [NMAX * 64];
__device__ float g_h1  [NMAX * 64];
__device__ float g_xw2 [NMAX * 32];
__device__ float g_hact[NMAX * 32];
__device__ float g_xw3 [NMAX * 16];

// ---------------- init + dtype probe ----------------------------------------
// int64 values < 2^31 have zero high (odd, little-endian) 32-bit words.
__global__ void k_init(const int* __restrict__ ei32, int n) {
    int i = blockIdx.x * blockDim.x + threadIdx.x;
    if (i < n) g_cnt[i] = 0;
    if (i == 0) {
        int z = 0;
#pragma unroll
        for (int j = 1; j < 16; j += 2) z |= ei32[j];
        g_is64 = (z == 0) ? 1 : 0;
    }
}

__device__ __forceinline__ int load_idx(const int* ei, int pos) {
    return g_is64 ? ei[2 * pos] : ei[pos];
}

__global__ void k_cnt(const int* __restrict__ ei, int E, int N) {
    int e = blockIdx.x * blockDim.x + threadIdx.x;
    if (e < E) {
        int r = load_idx(ei, e);
        int c = load_idx(ei, E + e);
        if ((unsigned)r >= (unsigned)N) r = 0;
        if ((unsigned)c >= (unsigned)N) c = 0;
        g_row[e] = r;
        g_col[e] = c;
        atomicAdd(&g_cnt[c], 1);
    }
}

// ---------------- 3-phase parallel exclusive scan of g_cnt ------------------
// phase 1: per-block exclusive scan (warp shuffles) + block totals
__global__ void k_scan1(int n) {
    __shared__ int swarp[32];
    int i = blockIdx.x * SCAN_T + threadIdx.x;
    int lane = threadIdx.x & 31;
    int warp = threadIdx.x >> 5;
    int v = (i < n) ? g_cnt[i] : 0;
    int x = v;
#pragma unroll
    for (int o = 1; o < 32; o <<= 1) {
        int y = __shfl_up_sync(0xffffffffu, x, o);
        if (lane >= o) x += y;
    }
    if (lane == 31) swarp[warp] = x;
    __syncthreads();
    if (warp == 0) {
        int w = swarp[lane];
#pragma unroll
        for (int o = 1; o < 32; o <<= 1) {
            int y = __shfl_up_sync(0xffffffffu, w, o);
            if (lane >= o) w += y;
        }
        swarp[lane] = w;
    }
    __syncthreads();
    int warpoff = (warp > 0) ? swarp[warp - 1] : 0;
    if (i < n) g_part[i] = warpoff + x - v;           // exclusive within block
    if (threadIdx.x == SCAN_T - 1) g_bsum[blockIdx.x] = warpoff + x;
}

// phase 2: shared-memory Hillis-Steele over <=128 block totals, in place
__global__ void k_scan2(int nb) {
    __shared__ int s[128];
    int t = threadIdx.x;                  // 128 threads
    int v = (t < nb) ? g_bsum[t] : 0;
    s[t] = v;
    __syncthreads();
#pragma unroll
    for (int o = 1; o < 128; o <<= 1) {
        int y = (t >= o) ? s[t - o] : 0;
        __syncthreads();
        s[t] += y;
        __syncthreads();
    }
    if (t < nb) g_bsum[t] = s[t] - v;     // exclusive
}

// phase 3: add block offsets, emit g_ptr / g_cur; g_ptr[n] = E (known)
__global__ void k_scan3(int n, int E) {
    int i = blockIdx.x * SCAN_T + threadIdx.x;
    if (i < n) {
        int p = g_part[i] + g_bsum[blockIdx.x];
        g_ptr[i] = p;
        g_cur[i] = p;
    }
    if (i == 0) g_ptr[n] = E;
}

__global__ void k_fill(const float* __restrict__ ew, int E) {
    int e = blockIdx.x * blockDim.x + threadIdx.x;
    if (e >= E) return;
    int pos = atomicAdd(&g_cur[g_col[e]], 1);
    g_srow[pos] = g_row[e];
    g_sval[pos] = ew[e];
}

// deg = 1 (self loop) + sum incoming edge weights; dinv = rsqrt(deg)
__global__ void k_degdinv(int N) {
    int node = (blockIdx.x * blockDim.x + threadIdx.x) >> 5;
    if (node >= N) return;
    int lane = threadIdx.x & 31;
    int beg = g_ptr[node], end = g_ptr[node + 1];
    float s = 0.0f;
    for (int p = beg + lane; p < end; p += 32) s += g_sval[p];
#pragma unroll
    for (int o = 16; o; o >>= 1) s += __shfl_xor_sync(0xffffffffu, s, o);
    if (lane == 0) g_dinv[node] = rsqrtf(1.0f + s);
}

__global__ void k_norm(int N) {
    int node = (blockIdx.x * blockDim.x + threadIdx.x) >> 5;
    if (node >= N) return;
    int lane = threadIdx.x & 31;
    int beg = g_ptr[node], end = g_ptr[node + 1];
    float dc = g_dinv[node];
    for (int p = beg + lane; p < end; p += 32)
        g_sval[p] = g_dinv[g_srow[p]] * g_sval[p] * dc;
}

// ---------------- register-tiled fp32 GEMM body -----------------------------
template<int K, int FOUT, int TN>
__device__ __forceinline__ void gemm_body(const float* __restrict__ X,
                                          const float* __restrict__ W,
                                          float* __restrict__ out, int N) {
    constexpr int BM = 64;
    constexpr int TM = 4;
    constexpr int KC = 32;
    __shared__ float sW[K * FOUT];
    __shared__ float sX[BM][KC + 1];

    const int tid = threadIdx.x;
    const int tx  = tid & 15;
    const int ty  = tid >> 4;
    const int row0 = blockIdx.x * BM;

    for (int i = tid; i < K * FOUT; i += 256) sW[i] = W[i];

    float acc[TM][TN];
#pragma unroll
    for (int i = 0; i < TM; i++)
#pragma unroll
        for (int j = 0; j < TN; j++) acc[i][j] = 0.0f;

    for (int k0 = 0; k0 < K; k0 += KC) {
        __syncthreads();
        for (int i = tid; i < BM * KC; i += 256) {
            int r = i / KC, c = i - r * KC;
            int gr = row0 + r;
            sX[r][c] = (gr < N) ? X[(size_t)gr * K + k0 + c] : 0.0f;
        }
        __syncthreads();
#pragma unroll
        for (int k = 0; k < KC; k++) {
            float xr[TM], wr[TN];
#pragma unroll
            for (int i = 0; i < TM; i++) xr[i] = sX[ty + 16 * i][k];
#pragma unroll
            for (int j = 0; j < TN; j++) wr[j] = sW[(k0 + k) * FOUT + tx + 16 * j];
#pragma unroll
            for (int i = 0; i < TM; i++)
#pragma unroll
                for (int j = 0; j < TN; j++)
                    acc[i][j] += xr[i] * wr[j];
        }
    }
#pragma unroll
    for (int i = 0; i < TM; i++) {
        int gr = row0 + ty + 16 * i;
        if (gr < N) {
#pragma unroll
            for (int j = 0; j < TN; j++)
                out[(size_t)gr * FOUT + tx + 16 * j] = acc[i][j];
        }
    }
}

__global__ void k_gemm1(const float* __restrict__ X, const float* __restrict__ W, int N) {
    gemm_body<128, 64, 4>(X, W, g_xw1, N);
}
__global__ void k_gemm2(const float* __restrict__ W, int N) {
    gemm_body<64, 32, 2>(g_h1, W, g_xw2, N);
}
__global__ void k_gemm3(const float* __restrict__ W, int N) {
    gemm_body<32, 16, 1>(g_hact, W, g_xw3, N);
}

// ---------------- CSR gather aggregation, one warp per node -----------------
__global__ void k_agg1(const float* __restrict__ b, int N) {
    int node = (blockIdx.x * blockDim.x + threadIdx.x) >> 5;
    if (node >= N) return;
    int lane = threadIdx.x & 31;
    int beg = g_ptr[node], end = g_ptr[node + 1];
    float a0 = 0.0f, a1 = 0.0f;
    for (int p = beg; p < end; p++) {
        int r = g_srow[p];
        float nm = g_sval[p];
        const float* src = g_xw1 + (size_t)r * 64;
        a0 += nm * src[lane];
        a1 += nm * src[lane + 32];
    }
    float di = g_dinv[node];
    float d2 = di * di;
    const float* self = g_xw1 + (size_t)node * 64;
    a0 += d2 * self[lane]      + b[lane];
    a1 += d2 * self[lane + 32] + b[lane + 32];
    g_h1[(size_t)node * 64 + lane]      = tanhf(a0);
    g_h1[(size_t)node * 64 + lane + 32] = tanhf(a1);
}

__global__ void k_agg2(const float* __restrict__ b, float* __restrict__ emb, int N) {
    int node = (blockIdx.x * blockDim.x + threadIdx.x) >> 5;
    if (node >= N) return;
    int lane = threadIdx.x & 31;
    int beg = g_ptr[node], end = g_ptr[node + 1];
    float a = 0.0f;
    for (int p = beg; p < end; p++) {
        int r = g_srow[p];
        float nm = g_sval[p];
        a += nm * g_xw2[(size_t)r * 32 + lane];
    }
    float di = g_dinv[node];
    float val = a + di * di * g_xw2[(size_t)node * 32 + lane] + b[lane];
    emb[(size_t)node * 32 + lane] = val;
    g_hact[(size_t)node * 32 + lane] = tanhf(val);
}

__global__ void k_agg3(const float* __restrict__ b, float* __restrict__ logits, int N) {
    int node = (blockIdx.x * blockDim.x + threadIdx.x) >> 5;
    if (node >= N) return;
    int lane = threadIdx.x & 31;
    int sub = lane >> 4;
    int f = lane & 15;
    int beg = g_ptr[node], end = g_ptr[node + 1];
    float a = 0.0f;
    for (int p = beg + sub; p < end; p += 2) {
        int r = g_srow[p];
        float nm = g_sval[p];
        a += nm * g_xw3[(size_t)r * 16 + f];
    }
    a += __shfl_xor_sync(0xffffffffu, a, 16);
    if (sub == 0) {
        float di = g_dinv[node];
        logits[(size_t)node * 16 + f] =
            a + di * di * g_xw3[(size_t)node * 16 + f] + b[f];
    }
}

// ---------------- launch: ONLY kernel launches, no CUDA host APIs -----------
extern "C" void kernel_launch(void* const* d_in, const int* in_sizes, int n_in,
                              void* d_out, int out_size) {
    const float* x  = (const float*)d_in[0];
    const int*   ei = (const int*)d_in[1];   // int32 or int64, probed on device
    const float* ew = (const float*)d_in[2];
    const float* W1 = (const float*)d_in[3];
    const float* b1 = (const float*)d_in[4];
    const float* W2 = (const float*)d_in[5];
    const float* b2 = (const float*)d_in[6];
    const float* W3 = (const float*)d_in[7];
    const float* b3 = (const float*)d_in[8];

    const int N = in_sizes[0] / 128;
    const int E = in_sizes[2];

    float* logits = (float*)d_out;                    // [N,16]
    float* emb    = (float*)d_out + (size_t)N * 16;   // [N,32]

    const int T = 256;
    auto cdiv = [](long long a, long long b) { return (int)((a + b - 1) / b); };
    const int warpGrid = cdiv((long long)N * 32, T);
    const int nb = cdiv(N, SCAN_T);                   // scan blocks (<= 128)

    // ---- CSR build (shared by all layers) ----
    k_init <<<cdiv(N, T), T>>>(ei, N);
    k_cnt  <<<cdiv(E, T), T>>>(ei, E, N);
    k_scan1<<<nb, SCAN_T>>>(N);
    k_scan2<<<1, 128>>>(nb);
    k_scan3<<<nb, SCAN_T>>>(N, E);
    k_fill <<<cdiv(E, T), T>>>(ew, E);
    k_degdinv<<<warpGrid, T>>>(N);
    k_norm   <<<warpGrid, T>>>(N);

    // ---- layer 1: h1 = tanh(conv(x, W1, b1)) ----
    k_gemm1<<<cdiv(N, 64), T>>>(x, W1, N);
    k_agg1 <<<warpGrid, T>>>(b1, N);

    // ---- layer 2: emb = conv(h1, W2, b2); hact = tanh(emb) ----
    k_gemm2<<<cdiv(N, 64), T>>>(W2, N);
    k_agg2 <<<warpGrid, T>>>(b2, emb, N);

    // ---- layer 3: logits = conv(hact, W3, b3) ----
    k_gemm3<<<cdiv(N, 64), T>>>(W3, N);
    k_agg3 <<<warpGrid, T>>>(b3, logits, N);
}

// round 7
// speedup vs baseline: 1.6178x; 1.1078x over previous
#include <cuda_runtime.h>
#include <cstdint>

#define NMAX 100000
#define EMAX 1600000
#define SCAN_T 1024
#define MAXBLK 128

// ---------------- scratch (device globals, device-side references only) -----
__device__ int   g_is64;
__device__ float g_deg  [NMAX];
__device__ float g_dinv [NMAX];
__device__ int   g_cnt  [NMAX];
__device__ int   g_part [NMAX];
__device__ int   g_bsum [MAXBLK];
__device__ int   g_ptr  [NMAX + 1];
__device__ int   g_cur  [NMAX];
__device__ int2  g_rc   [EMAX];      // (row, col) per input edge
__device__ int2  g_edge [EMAX];      // CSR slot: (src row, norm bits)
__device__ float g_xw1 [NMAX * 64];
__device__ float g_h1  [NMAX * 64];
__device__ float g_xw2 [NMAX * 32];
__device__ float g_hact[NMAX * 32];
__device__ float g_xw3 [NMAX * 16];

// ---------------- init + dtype probe ----------------------------------------
__global__ void k_init(const int* __restrict__ ei32, int n) {
    int i = blockIdx.x * blockDim.x + threadIdx.x;
    if (i < n) { g_cnt[i] = 0; g_deg[i] = 1.0f; }   // 1 = self-loop weight
    if (i == 0) {
        int z = 0;
#pragma unroll
        for (int j = 1; j < 16; j += 2) z |= ei32[j];
        g_is64 = (z == 0) ? 1 : 0;
    }
}

__device__ __forceinline__ int load_idx(const int* ei, int pos) {
    return g_is64 ? ei[2 * pos] : ei[pos];
}

// count + degree accumulation in one pass
__global__ void k_cnt(const int* __restrict__ ei, const float* __restrict__ ew,
                      int E, int N) {
    int e = blockIdx.x * blockDim.x + threadIdx.x;
    if (e < E) {
        int r = load_idx(ei, e);
        int c = load_idx(ei, E + e);
        if ((unsigned)r >= (unsigned)N) r = 0;
        if ((unsigned)c >= (unsigned)N) c = 0;
        g_rc[e] = make_int2(r, c);
        atomicAdd(&g_cnt[c], 1);
        atomicAdd(&g_deg[c], ew[e]);
    }
}

// ---------------- 3-phase parallel exclusive scan of g_cnt ------------------
__global__ void k_scan1(int n) {
    __shared__ int swarp[32];
    int i = blockIdx.x * SCAN_T + threadIdx.x;
    int lane = threadIdx.x & 31;
    int warp = threadIdx.x >> 5;
    int v = (i < n) ? g_cnt[i] : 0;
    int x = v;
#pragma unroll
    for (int o = 1; o < 32; o <<= 1) {
        int y = __shfl_up_sync(0xffffffffu, x, o);
        if (lane >= o) x += y;
    }
    if (lane == 31) swarp[warp] = x;
    __syncthreads();
    if (warp == 0) {
        int w = swarp[lane];
#pragma unroll
        for (int o = 1; o < 32; o <<= 1) {
            int y = __shfl_up_sync(0xffffffffu, w, o);
            if (lane >= o) w += y;
        }
        swarp[lane] = w;
    }
    __syncthreads();
    int warpoff = (warp > 0) ? swarp[warp - 1] : 0;
    if (i < n) g_part[i] = warpoff + x - v;
    if (threadIdx.x == SCAN_T - 1) g_bsum[blockIdx.x] = warpoff + x;
}

__global__ void k_scan2(int nb) {
    __shared__ int s[128];
    int t = threadIdx.x;
    int v = (t < nb) ? g_bsum[t] : 0;
    s[t] = v;
    __syncthreads();
#pragma unroll
    for (int o = 1; o < 128; o <<= 1) {
        int y = (t >= o) ? s[t - o] : 0;
        __syncthreads();
        s[t] += y;
        __syncthreads();
    }
    if (t < nb) g_bsum[t] = s[t] - v;
}

// phase 3: emit ptr/cur AND dinv = rsqrt(deg) (deg final after k_cnt)
__global__ void k_scan3(int n, int E) {
    int i = blockIdx.x * SCAN_T + threadIdx.x;
    if (i < n) {
        int p = g_part[i] + g_bsum[blockIdx.x];
        g_ptr[i] = p;
        g_cur[i] = p;
        g_dinv[i] = rsqrtf(g_deg[i]);
    }
    if (i == 0) g_ptr[n] = E;
}

// fill CSR slots with (src row, FINAL symmetric norm)
__global__ void k_fill(const float* __restrict__ ew, int E) {
    int e = blockIdx.x * blockDim.x + threadIdx.x;
    if (e >= E) return;
    int2 rc = g_rc[e];
    float nm = g_dinv[rc.x] * ew[e] * g_dinv[rc.y];
    int pos = atomicAdd(&g_cur[rc.y], 1);
    g_edge[pos] = make_int2(rc.x, __float_as_int(nm));
}

// ---------------- register-tiled fp32 GEMM body -----------------------------
template<int K, int FOUT, int TN>
__device__ __forceinline__ void gemm_body(const float* __restrict__ X,
                                          const float* __restrict__ W,
                                          float* __restrict__ out, int N) {
    constexpr int BM = 64;
    constexpr int TM = 4;
    constexpr int KC = 32;
    __shared__ float sW[K * FOUT];
    __shared__ float sX[BM][KC + 1];

    const int tid = threadIdx.x;
    const int tx  = tid & 15;
    const int ty  = tid >> 4;
    const int row0 = blockIdx.x * BM;

    for (int i = tid; i < K * FOUT; i += 256) sW[i] = W[i];

    float acc[TM][TN];
#pragma unroll
    for (int i = 0; i < TM; i++)
#pragma unroll
        for (int j = 0; j < TN; j++) acc[i][j] = 0.0f;

    for (int k0 = 0; k0 < K; k0 += KC) {
        __syncthreads();
        for (int i = tid; i < BM * KC; i += 256) {
            int r = i / KC, c = i - r * KC;
            int gr = row0 + r;
            sX[r][c] = (gr < N) ? X[(size_t)gr * K + k0 + c] : 0.0f;
        }
        __syncthreads();
#pragma unroll
        for (int k = 0; k < KC; k++) {
            float xr[TM], wr[TN];
#pragma unroll
            for (int i = 0; i < TM; i++) xr[i] = sX[ty + 16 * i][k];
#pragma unroll
            for (int j = 0; j < TN; j++) wr[j] = sW[(k0 + k) * FOUT + tx + 16 * j];
#pragma unroll
            for (int i = 0; i < TM; i++)
#pragma unroll
                for (int j = 0; j < TN; j++)
                    acc[i][j] += xr[i] * wr[j];
        }
    }
#pragma unroll
    for (int i = 0; i < TM; i++) {
        int gr = row0 + ty + 16 * i;
        if (gr < N) {
#pragma unroll
            for (int j = 0; j < TN; j++)
                out[(size_t)gr * FOUT + tx + 16 * j] = acc[i][j];
        }
    }
}

__global__ void k_gemm1(const float* __restrict__ X, const float* __restrict__ W, int N) {
    gemm_body<128, 64, 4>(X, W, g_xw1, N);
}
__global__ void k_gemm2(const float* __restrict__ W, int N) {
    gemm_body<64, 32, 2>(g_h1, W, g_xw2, N);
}
__global__ void k_gemm3(const float* __restrict__ W, int N) {
    gemm_body<32, 16, 1>(g_hact, W, g_xw3, N);
}

// ---------------- CSR gather aggregation, one warp per node, 4x unroll ------
__global__ void k_agg1(const float* __restrict__ b, int N) {
    int node = (blockIdx.x * blockDim.x + threadIdx.x) >> 5;
    if (node >= N) return;
    int lane = threadIdx.x & 31;
    int beg = g_ptr[node], end = g_ptr[node + 1];
    float a0 = 0.0f, a1 = 0.0f;
    int p = beg;
    for (; p + 4 <= end; p += 4) {
        int2 e0 = g_edge[p], e1 = g_edge[p + 1], e2 = g_edge[p + 2], e3 = g_edge[p + 3];
        const float* s0 = g_xw1 + (size_t)e0.x * 64;
        const float* s1 = g_xw1 + (size_t)e1.x * 64;
        const float* s2 = g_xw1 + (size_t)e2.x * 64;
        const float* s3 = g_xw1 + (size_t)e3.x * 64;
        float n0 = __int_as_float(e0.y), n1 = __int_as_float(e1.y);
        float n2 = __int_as_float(e2.y), n3 = __int_as_float(e3.y);
        float v0a = s0[lane], v0b = s0[lane + 32];
        float v1a = s1[lane], v1b = s1[lane + 32];
        float v2a = s2[lane], v2b = s2[lane + 32];
        float v3a = s3[lane], v3b = s3[lane + 32];
        a0 += n0 * v0a; a1 += n0 * v0b;
        a0 += n1 * v1a; a1 += n1 * v1b;
        a0 += n2 * v2a; a1 += n2 * v2b;
        a0 += n3 * v3a; a1 += n3 * v3b;
    }
    for (; p < end; p++) {
        int2 e = g_edge[p];
        const float* s = g_xw1 + (size_t)e.x * 64;
        float nm = __int_as_float(e.y);
        a0 += nm * s[lane];
        a1 += nm * s[lane + 32];
    }
    float di = g_dinv[node];
    float d2 = di * di;
    const float* self = g_xw1 + (size_t)node * 64;
    a0 += d2 * self[lane]      + b[lane];
    a1 += d2 * self[lane + 32] + b[lane + 32];
    g_h1[(size_t)node * 64 + lane]      = tanhf(a0);
    g_h1[(size_t)node * 64 + lane + 32] = tanhf(a1);
}

__global__ void k_agg2(const float* __restrict__ b, float* __restrict__ emb, int N) {
    int node = (blockIdx.x * blockDim.x + threadIdx.x) >> 5;
    if (node >= N) return;
    int lane = threadIdx.x & 31;
    int beg = g_ptr[node], end = g_ptr[node + 1];
    float a = 0.0f;
    int p = beg;
    for (; p + 4 <= end; p += 4) {
        int2 e0 = g_edge[p], e1 = g_edge[p + 1], e2 = g_edge[p + 2], e3 = g_edge[p + 3];
        float v0 = g_xw2[(size_t)e0.x * 32 + lane];
        float v1 = g_xw2[(size_t)e1.x * 32 + lane];
        float v2 = g_xw2[(size_t)e2.x * 32 + lane];
        float v3 = g_xw2[(size_t)e3.x * 32 + lane];
        a += __int_as_float(e0.y) * v0;
        a += __int_as_float(e1.y) * v1;
        a += __int_as_float(e2.y) * v2;
        a += __int_as_float(e3.y) * v3;
    }
    for (; p < end; p++) {
        int2 e = g_edge[p];
        a += __int_as_float(e.y) * g_xw2[(size_t)e.x * 32 + lane];
    }
    float di = g_dinv[node];
    float val = a + di * di * g_xw2[(size_t)node * 32 + lane] + b[lane];
    emb[(size_t)node * 32 + lane] = val;
    g_hact[(size_t)node * 32 + lane] = tanhf(val);
}

__global__ void k_agg3(const float* __restrict__ b, float* __restrict__ logits, int N) {
    int node = (blockIdx.x * blockDim.x + threadIdx.x) >> 5;
    if (node >= N) return;
    int lane = threadIdx.x & 31;
    int sub = lane >> 4;
    int f = lane & 15;
    int beg = g_ptr[node], end = g_ptr[node + 1];
    float a = 0.0f;
    int p = beg + sub;
    for (; p + 8 <= end; p += 8) {          // 4 edges per half-warp
        int2 e0 = g_edge[p],     e1 = g_edge[p + 2];
        int2 e2 = g_edge[p + 4], e3 = g_edge[p + 6];
        float v0 = g_xw3[(size_t)e0.x * 16 + f];
        float v1 = g_xw3[(size_t)e1.x * 16 + f];
        float v2 = g_xw3[(size_t)e2.x * 16 + f];
        float v3 = g_xw3[(size_t)e3.x * 16 + f];
        a += __int_as_float(e0.y) * v0;
        a += __int_as_float(e1.y) * v1;
        a += __int_as_float(e2.y) * v2;
        a += __int_as_float(e3.y) * v3;
    }
    for (; p < end; p += 2) {
        int2 e = g_edge[p];
        a += __int_as_float(e.y) * g_xw3[(size_t)e.x * 16 + f];
    }
    a += __shfl_xor_sync(0xffffffffu, a, 16);
    if (sub == 0) {
        float di = g_dinv[node];
        logits[(size_t)node * 16 + f] =
            a + di * di * g_xw3[(size_t)node * 16 + f] + b[f];
    }
}

// ---------------- launch ----------------------------------------------------
extern "C" void kernel_launch(void* const* d_in, const int* in_sizes, int n_in,
                              void* d_out, int out_size) {
    const float* x  = (const float*)d_in[0];
    const int*   ei = (const int*)d_in[1];
    const float* ew = (const float*)d_in[2];
    const float* W1 = (const float*)d_in[3];
    const float* b1 = (const float*)d_in[4];
    const float* W2 = (const float*)d_in[5];
    const float* b2 = (const float*)d_in[6];
    const float* W3 = (const float*)d_in[7];
    const float* b3 = (const float*)d_in[8];

    const int N = in_sizes[0] / 128;
    const int E = in_sizes[2];

    float* logits = (float*)d_out;                    // [N,16]
    float* emb    = (float*)d_out + (size_t)N * 16;   // [N,32]

    const int T = 256;
    auto cdiv = [](long long a, long long b) { return (int)((a + b - 1) / b); };
    const int warpGrid = cdiv((long long)N * 32, T);
    const int nb = cdiv(N, SCAN_T);

    // ---- CSR build ----
    k_init <<<cdiv(N, T), T>>>(ei, N);
    k_cnt  <<<cdiv(E, T), T>>>(ei, ew, E, N);
    k_scan1<<<nb, SCAN_T>>>(N);
    k_scan2<<<1, 128>>>(nb);
    k_scan3<<<nb, SCAN_T>>>(N, E);
    k_fill <<<cdiv(E, T), T>>>(ew, E);

    // ---- layer 1 ----
    k_gemm1<<<cdiv(N, 64), T>>>(x, W1, N);
    k_agg1 <<<warpGrid, T>>>(b1, N);

    // ---- layer 2 ----
    k_gemm2<<<cdiv(N, 64), T>>>(W2, N);
    k_agg2 <<<warpGrid, T>>>(b2, emb, N);

    // ---- layer 3 ----
    k_gemm3<<<cdiv(N, 64), T>>>(W3, N);
    k_agg3 <<<warpGrid, T>>>(b3, logits, N);
}

// round 8
// speedup vs baseline: 1.7726x; 1.0957x over previous
#include <cuda_runtime.h>
#include <cstdint>

#define NMAX 100000
#define EMAX 1600000
#define SCAN_T 1024
#define MAXBLK 128

// ---------------- scratch (device globals, device-side references only) -----
__device__ int   g_is64;
__device__ float g_deg  [NMAX];
__device__ float g_dinv [NMAX];
__device__ int   g_cnt  [NMAX];
__device__ int   g_part [NMAX];
__device__ int   g_bsum [MAXBLK];
__device__ int   g_ptr  [NMAX + 1];
__device__ int   g_cur  [NMAX];
__device__ int2  g_edge [EMAX];      // CSR slot: (src row, norm bits)
__device__ float g_xw1 [NMAX * 64];
__device__ float g_h1  [NMAX * 64];
__device__ float g_xw2 [NMAX * 32];
__device__ float g_hact[NMAX * 32];
__device__ float g_xw3 [NMAX * 16];

// ---------------- init + dtype probe ----------------------------------------
__global__ void k_init(const int* __restrict__ ei32, int n) {
    int i = blockIdx.x * blockDim.x + threadIdx.x;
    if (i < n) { g_cnt[i] = 0; g_deg[i] = 1.0f; }   // 1 = self-loop weight
    if (i == 0) {
        int z = 0;
#pragma unroll
        for (int j = 1; j < 16; j += 2) z |= ei32[j];
        g_is64 = (z == 0) ? 1 : 0;
    }
}

__device__ __forceinline__ int load_idx(const int* ei, int pos) {
    return g_is64 ? ei[2 * pos] : ei[pos];
}

// count + degree accumulation in one pass
__global__ void k_cnt(const int* __restrict__ ei, const float* __restrict__ ew,
                      int E, int N) {
    int e = blockIdx.x * blockDim.x + threadIdx.x;
    if (e < E) {
        int c = load_idx(ei, E + e);
        if ((unsigned)c >= (unsigned)N) c = 0;
        atomicAdd(&g_cnt[c], 1);
        atomicAdd(&g_deg[c], ew[e]);
    }
}

// ---------------- 3-phase parallel exclusive scan of g_cnt ------------------
__global__ void k_scan1(int n) {
    __shared__ int swarp[32];
    int i = blockIdx.x * SCAN_T + threadIdx.x;
    int lane = threadIdx.x & 31;
    int warp = threadIdx.x >> 5;
    int v = (i < n) ? g_cnt[i] : 0;
    int x = v;
#pragma unroll
    for (int o = 1; o < 32; o <<= 1) {
        int y = __shfl_up_sync(0xffffffffu, x, o);
        if (lane >= o) x += y;
    }
    if (lane == 31) swarp[warp] = x;
    __syncthreads();
    if (warp == 0) {
        int w = swarp[lane];
#pragma unroll
        for (int o = 1; o < 32; o <<= 1) {
            int y = __shfl_up_sync(0xffffffffu, w, o);
            if (lane >= o) w += y;
        }
        swarp[lane] = w;
    }
    __syncthreads();
    int warpoff = (warp > 0) ? swarp[warp - 1] : 0;
    if (i < n) g_part[i] = warpoff + x - v;
    if (threadIdx.x == SCAN_T - 1) g_bsum[blockIdx.x] = warpoff + x;
}

__global__ void k_scan2(int nb) {
    __shared__ int s[128];
    int t = threadIdx.x;
    int v = (t < nb) ? g_bsum[t] : 0;
    s[t] = v;
    __syncthreads();
#pragma unroll
    for (int o = 1; o < 128; o <<= 1) {
        int y = (t >= o) ? s[t - o] : 0;
        __syncthreads();
        s[t] += y;
        __syncthreads();
    }
    if (t < nb) g_bsum[t] = s[t] - v;
}

// phase 3: emit ptr/cur AND dinv = rsqrt(deg)
__global__ void k_scan3(int n, int E) {
    int i = blockIdx.x * SCAN_T + threadIdx.x;
    if (i < n) {
        int p = g_part[i] + g_bsum[blockIdx.x];
        g_ptr[i] = p;
        g_cur[i] = p;
        g_dinv[i] = rsqrtf(g_deg[i]);
    }
    if (i == 0) g_ptr[n] = E;
}

// fill CSR slots with (src row, FINAL symmetric norm)
__global__ void k_fill(const int* __restrict__ ei, const float* __restrict__ ew,
                       int E, int N) {
    int e = blockIdx.x * blockDim.x + threadIdx.x;
    if (e >= E) return;
    int r = load_idx(ei, e);
    int c = load_idx(ei, E + e);
    if ((unsigned)r >= (unsigned)N) r = 0;
    if ((unsigned)c >= (unsigned)N) c = 0;
    float nm = g_dinv[r] * ew[e] * g_dinv[c];
    int pos = atomicAdd(&g_cur[c], 1);
    g_edge[pos] = make_int2(r, __float_as_int(nm));
}

// ---------------- fp32 GEMM: BM=128, thread tile 8 x TN, transposed X smem --
// out[N,FOUT] = X[N,K] @ W[K,FOUT];  256 threads; K,KC mult of 32; FOUT=16*TN
template<int K, int FOUT, int TN>
__device__ __forceinline__ void gemm_body(const float* __restrict__ X,
                                          const float* __restrict__ W,
                                          float* __restrict__ out, int N) {
    constexpr int BM = 128;
    constexpr int TM = 8;
    constexpr int KC = 32;
    __shared__ float sW[K * FOUT];
    __shared__ float sXT[KC][BM + 1];     // transposed: [k][row]

    const int tid = threadIdx.x;
    const int tx  = tid & 15;
    const int ty  = tid >> 4;
    const int row0 = blockIdx.x * BM;

    // vectorized W load
    {
        const float4* W4 = reinterpret_cast<const float4*>(W);
        float4* sW4 = reinterpret_cast<float4*>(sW);
        for (int i = tid; i < K * FOUT / 4; i += 256) sW4[i] = W4[i];
    }

    float acc[TM][TN];
#pragma unroll
    for (int i = 0; i < TM; i++)
#pragma unroll
        for (int j = 0; j < TN; j++) acc[i][j] = 0.0f;

    for (int k0 = 0; k0 < K; k0 += KC) {
        __syncthreads();
        // load X tile: BM x KC as float4, store transposed
#pragma unroll
        for (int t = 0; t < (BM * KC / 4) / 256; t++) {
            int v = tid + 256 * t;
            int row = v >> 3;             // KC/4 = 8 vectors per row
            int cp  = v & 7;
            int gr = row0 + row;
            float4 val = make_float4(0.f, 0.f, 0.f, 0.f);
            if (gr < N)
                val = *reinterpret_cast<const float4*>(X + (size_t)gr * K + k0 + cp * 4);
            sXT[cp * 4 + 0][row] = val.x;
            sXT[cp * 4 + 1][row] = val.y;
            sXT[cp * 4 + 2][row] = val.z;
            sXT[cp * 4 + 3][row] = val.w;
        }
        __syncthreads();
#pragma unroll
        for (int k = 0; k < KC; k++) {
            float xr[TM], wr[TN];
#pragma unroll
            for (int i = 0; i < TM; i++) xr[i] = sXT[k][ty + 16 * i];
#pragma unroll
            for (int j = 0; j < TN; j++) wr[j] = sW[(k0 + k) * FOUT + tx + 16 * j];
#pragma unroll
            for (int i = 0; i < TM; i++)
#pragma unroll
                for (int j = 0; j < TN; j++)
                    acc[i][j] += xr[i] * wr[j];
        }
    }
#pragma unroll
    for (int i = 0; i < TM; i++) {
        int gr = row0 + ty + 16 * i;
        if (gr < N) {
#pragma unroll
            for (int j = 0; j < TN; j++)
                out[(size_t)gr * FOUT + tx + 16 * j] = acc[i][j];
        }
    }
}

__global__ void k_gemm1(const float* __restrict__ X, const float* __restrict__ W, int N) {
    gemm_body<128, 64, 4>(X, W, g_xw1, N);
}
__global__ void k_gemm2(const float* __restrict__ W, int N) {
    gemm_body<64, 32, 2>(g_h1, W, g_xw2, N);
}
__global__ void k_gemm3(const float* __restrict__ W, int N) {
    gemm_body<32, 16, 1>(g_hact, W, g_xw3, N);
}

// ---------------- CSR gather aggregation, one warp per node, 4x unroll ------
__global__ void k_agg1(const float* __restrict__ b, int N) {
    int node = (blockIdx.x * blockDim.x + threadIdx.x) >> 5;
    if (node >= N) return;
    int lane = threadIdx.x & 31;
    int beg = g_ptr[node], end = g_ptr[node + 1];
    float a0 = 0.0f, a1 = 0.0f;
    int p = beg;
    for (; p + 4 <= end; p += 4) {
        int2 e0 = g_edge[p], e1 = g_edge[p + 1], e2 = g_edge[p + 2], e3 = g_edge[p + 3];
        const float* s0 = g_xw1 + (size_t)e0.x * 64;
        const float* s1 = g_xw1 + (size_t)e1.x * 64;
        const float* s2 = g_xw1 + (size_t)e2.x * 64;
        const float* s3 = g_xw1 + (size_t)e3.x * 64;
        float n0 = __int_as_float(e0.y), n1 = __int_as_float(e1.y);
        float n2 = __int_as_float(e2.y), n3 = __int_as_float(e3.y);
        float v0a = s0[lane], v0b = s0[lane + 32];
        float v1a = s1[lane], v1b = s1[lane + 32];
        float v2a = s2[lane], v2b = s2[lane + 32];
        float v3a = s3[lane], v3b = s3[lane + 32];
        a0 += n0 * v0a; a1 += n0 * v0b;
        a0 += n1 * v1a; a1 += n1 * v1b;
        a0 += n2 * v2a; a1 += n2 * v2b;
        a0 += n3 * v3a; a1 += n3 * v3b;
    }
    for (; p < end; p++) {
        int2 e = g_edge[p];
        const float* s = g_xw1 + (size_t)e.x * 64;
        float nm = __int_as_float(e.y);
        a0 += nm * s[lane];
        a1 += nm * s[lane + 32];
    }
    float di = g_dinv[node];
    float d2 = di * di;
    const float* self = g_xw1 + (size_t)node * 64;
    a0 += d2 * self[lane]      + b[lane];
    a1 += d2 * self[lane + 32] + b[lane + 32];
    g_h1[(size_t)node * 64 + lane]      = tanhf(a0);
    g_h1[(size_t)node * 64 + lane + 32] = tanhf(a1);
}

__global__ void k_agg2(const float* __restrict__ b, float* __restrict__ emb, int N) {
    int node = (blockIdx.x * blockDim.x + threadIdx.x) >> 5;
    if (node >= N) return;
    int lane = threadIdx.x & 31;
    int beg = g_ptr[node], end = g_ptr[node + 1];
    float a = 0.0f;
    int p = beg;
    for (; p + 4 <= end; p += 4) {
        int2 e0 = g_edge[p], e1 = g_edge[p + 1], e2 = g_edge[p + 2], e3 = g_edge[p + 3];
        float v0 = g_xw2[(size_t)e0.x * 32 + lane];
        float v1 = g_xw2[(size_t)e1.x * 32 + lane];
        float v2 = g_xw2[(size_t)e2.x * 32 + lane];
        float v3 = g_xw2[(size_t)e3.x * 32 + lane];
        a += __int_as_float(e0.y) * v0;
        a += __int_as_float(e1.y) * v1;
        a += __int_as_float(e2.y) * v2;
        a += __int_as_float(e3.y) * v3;
    }
    for (; p < end; p++) {
        int2 e = g_edge[p];
        a += __int_as_float(e.y) * g_xw2[(size_t)e.x * 32 + lane];
    }
    float di = g_dinv[node];
    float val = a + di * di * g_xw2[(size_t)node * 32 + lane] + b[lane];
    emb[(size_t)node * 32 + lane] = val;
    g_hact[(size_t)node * 32 + lane] = tanhf(val);
}

__global__ void k_agg3(const float* __restrict__ b, float* __restrict__ logits, int N) {
    int node = (blockIdx.x * blockDim.x + threadIdx.x) >> 5;
    if (node >= N) return;
    int lane = threadIdx.x & 31;
    int sub = lane >> 4;
    int f = lane & 15;
    int beg = g_ptr[node], end = g_ptr[node + 1];
    float a = 0.0f;
    int p = beg + sub;
    for (; p + 8 <= end; p += 8) {
        int2 e0 = g_edge[p],     e1 = g_edge[p + 2];
        int2 e2 = g_edge[p + 4], e3 = g_edge[p + 6];
        float v0 = g_xw3[(size_t)e0.x * 16 + f];
        float v1 = g_xw3[(size_t)e1.x * 16 + f];
        float v2 = g_xw3[(size_t)e2.x * 16 + f];
        float v3 = g_xw3[(size_t)e3.x * 16 + f];
        a += __int_as_float(e0.y) * v0;
        a += __int_as_float(e1.y) * v1;
        a += __int_as_float(e2.y) * v2;
        a += __int_as_float(e3.y) * v3;
    }
    for (; p < end; p += 2) {
        int2 e = g_edge[p];
        a += __int_as_float(e.y) * g_xw3[(size_t)e.x * 16 + f];
    }
    a += __shfl_xor_sync(0xffffffffu, a, 16);
    if (sub == 0) {
        float di = g_dinv[node];
        logits[(size_t)node * 16 + f] =
            a + di * di * g_xw3[(size_t)node * 16 + f] + b[f];
    }
}

// ---------------- launch ----------------------------------------------------
extern "C" void kernel_launch(void* const* d_in, const int* in_sizes, int n_in,
                              void* d_out, int out_size) {
    const float* x  = (const float*)d_in[0];
    const int*   ei = (const int*)d_in[1];
    const float* ew = (const float*)d_in[2];
    const float* W1 = (const float*)d_in[3];
    const float* b1 = (const float*)d_in[4];
    const float* W2 = (const float*)d_in[5];
    const float* b2 = (const float*)d_in[6];
    const float* W3 = (const float*)d_in[7];
    const float* b3 = (const float*)d_in[8];

    const int N = in_sizes[0] / 128;
    const int E = in_sizes[2];

    float* logits = (float*)d_out;                    // [N,16]
    float* emb    = (float*)d_out + (size_t)N * 16;   // [N,32]

    const int T = 256;
    auto cdiv = [](long long a, long long b) { return (int)((a + b - 1) / b); };
    const int warpGrid = cdiv((long long)N * 32, T);
    const int nb = cdiv(N, SCAN_T);

    // ---- CSR build ----
    k_init <<<cdiv(N, T), T>>>(ei, N);
    k_cnt  <<<cdiv(E, T), T>>>(ei, ew, E, N);
    k_scan1<<<nb, SCAN_T>>>(N);
    k_scan2<<<1, 128>>>(nb);
    k_scan3<<<nb, SCAN_T>>>(N, E);
    k_fill <<<cdiv(E, T), T>>>(ei, ew, E, N);

    // ---- layer 1 ----
    k_gemm1<<<cdiv(N, 128), T>>>(x, W1, N);
    k_agg1 <<<warpGrid, T>>>(b1, N);

    // ---- layer 2 ----
    k_gemm2<<<cdiv(N, 128), T>>>(W2, N);
    k_agg2 <<<warpGrid, T>>>(b2, emb, N);

    // ---- layer 3 ----
    k_gemm3<<<cdiv(N, 128), T>>>(W3, N);
    k_agg3 <<<warpGrid, T>>>(b3, logits, N);
}

// round 9
// speedup vs baseline: 1.7968x; 1.0137x over previous
#include <cuda_runtime.h>
#include <cstdint>

#define NMAX 100000
#define EMAX 1600000
#define SCAN_T 1024
#define MAXBLK 128

// ---------------- scratch (device globals, device-side references only) -----
__device__ int   g_is64;
__device__ float g_deg  [NMAX];
__device__ float g_dinv [NMAX];
__device__ int   g_cnt  [NMAX];
__device__ int   g_part [NMAX];
__device__ int   g_bsum [MAXBLK];
__device__ int   g_ptr  [NMAX + 1];
__device__ int   g_cur  [NMAX];
__device__ int2  g_edge [EMAX];      // CSR slot: (src row, norm bits)
__device__ float g_xw1 [NMAX * 64];
__device__ float g_h1  [NMAX * 64];
__device__ float g_xw2 [NMAX * 32];
__device__ float g_xw3 [NMAX * 16];

// ---------------- init + dtype probe ----------------------------------------
__global__ void k_init(const int* __restrict__ ei32, int n) {
    int i = blockIdx.x * blockDim.x + threadIdx.x;
    if (i < n) { g_cnt[i] = 0; g_deg[i] = 1.0f; }   // 1 = self-loop weight
    if (i == 0) {
        int z = 0;
#pragma unroll
        for (int j = 1; j < 16; j += 2) z |= ei32[j];
        g_is64 = (z == 0) ? 1 : 0;
    }
}

__device__ __forceinline__ int load_idx(const int* ei, int pos) {
    return g_is64 ? ei[2 * pos] : ei[pos];
}

// count + degree accumulation in one pass
__global__ void k_cnt(const int* __restrict__ ei, const float* __restrict__ ew,
                      int E, int N) {
    int e = blockIdx.x * blockDim.x + threadIdx.x;
    if (e < E) {
        int c = load_idx(ei, E + e);
        if ((unsigned)c >= (unsigned)N) c = 0;
        atomicAdd(&g_cnt[c], 1);
        atomicAdd(&g_deg[c], ew[e]);
    }
}

// ---------------- 3-phase parallel exclusive scan of g_cnt ------------------
__global__ void k_scan1(int n) {
    __shared__ int swarp[32];
    int i = blockIdx.x * SCAN_T + threadIdx.x;
    int lane = threadIdx.x & 31;
    int warp = threadIdx.x >> 5;
    int v = (i < n) ? g_cnt[i] : 0;
    int x = v;
#pragma unroll
    for (int o = 1; o < 32; o <<= 1) {
        int y = __shfl_up_sync(0xffffffffu, x, o);
        if (lane >= o) x += y;
    }
    if (lane == 31) swarp[warp] = x;
    __syncthreads();
    if (warp == 0) {
        int w = swarp[lane];
#pragma unroll
        for (int o = 1; o < 32; o <<= 1) {
            int y = __shfl_up_sync(0xffffffffu, w, o);
            if (lane >= o) w += y;
        }
        swarp[lane] = w;
    }
    __syncthreads();
    int warpoff = (warp > 0) ? swarp[warp - 1] : 0;
    if (i < n) g_part[i] = warpoff + x - v;
    if (threadIdx.x == SCAN_T - 1) g_bsum[blockIdx.x] = warpoff + x;
}

__global__ void k_scan2(int nb) {
    __shared__ int s[128];
    int t = threadIdx.x;
    int v = (t < nb) ? g_bsum[t] : 0;
    s[t] = v;
    __syncthreads();
#pragma unroll
    for (int o = 1; o < 128; o <<= 1) {
        int y = (t >= o) ? s[t - o] : 0;
        __syncthreads();
        s[t] += y;
        __syncthreads();
    }
    if (t < nb) g_bsum[t] = s[t] - v;
}

// phase 3: emit ptr/cur AND dinv = rsqrt(deg)
__global__ void k_scan3(int n, int E) {
    int i = blockIdx.x * SCAN_T + threadIdx.x;
    if (i < n) {
        int p = g_part[i] + g_bsum[blockIdx.x];
        g_ptr[i] = p;
        g_cur[i] = p;
        g_dinv[i] = rsqrtf(g_deg[i]);
    }
    if (i == 0) g_ptr[n] = E;
}

// fill CSR slots with (src row, FINAL symmetric norm)
__global__ void k_fill(const int* __restrict__ ei, const float* __restrict__ ew,
                       int E, int N) {
    int e = blockIdx.x * blockDim.x + threadIdx.x;
    if (e >= E) return;
    int r = load_idx(ei, e);
    int c = load_idx(ei, E + e);
    if ((unsigned)r >= (unsigned)N) r = 0;
    if ((unsigned)c >= (unsigned)N) c = 0;
    float nm = g_dinv[r] * ew[e] * g_dinv[c];
    int pos = atomicAdd(&g_cur[c], 1);
    g_edge[pos] = make_int2(r, __float_as_int(nm));
}

// ---------------- fp32 GEMM: BM=128, thread tile 8 x TN, transposed X smem --
template<int K, int FOUT, int TN, bool TANH>
__device__ __forceinline__ void gemm_body(const float* __restrict__ X,
                                          const float* __restrict__ W,
                                          float* __restrict__ out, int N) {
    constexpr int BM = 128;
    constexpr int TM = 8;
    constexpr int KC = 32;
    __shared__ float sW[K * FOUT];
    __shared__ float sXT[KC][BM + 1];     // transposed: [k][row]

    const int tid = threadIdx.x;
    const int tx  = tid & 15;
    const int ty  = tid >> 4;
    const int row0 = blockIdx.x * BM;

    {
        const float4* W4 = reinterpret_cast<const float4*>(W);
        float4* sW4 = reinterpret_cast<float4*>(sW);
        for (int i = tid; i < K * FOUT / 4; i += 256) sW4[i] = W4[i];
    }

    float acc[TM][TN];
#pragma unroll
    for (int i = 0; i < TM; i++)
#pragma unroll
        for (int j = 0; j < TN; j++) acc[i][j] = 0.0f;

    for (int k0 = 0; k0 < K; k0 += KC) {
        __syncthreads();
#pragma unroll
        for (int t = 0; t < (BM * KC / 4) / 256; t++) {
            int v = tid + 256 * t;
            int row = v >> 3;             // KC/4 = 8 vectors per row
            int cp  = v & 7;
            int gr = row0 + row;
            float4 val = make_float4(0.f, 0.f, 0.f, 0.f);
            if (gr < N)
                val = *reinterpret_cast<const float4*>(X + (size_t)gr * K + k0 + cp * 4);
            if (TANH) {
                val.x = tanhf(val.x); val.y = tanhf(val.y);
                val.z = tanhf(val.z); val.w = tanhf(val.w);
            }
            sXT[cp * 4 + 0][row] = val.x;
            sXT[cp * 4 + 1][row] = val.y;
            sXT[cp * 4 + 2][row] = val.z;
            sXT[cp * 4 + 3][row] = val.w;
        }
        __syncthreads();
#pragma unroll
        for (int k = 0; k < KC; k++) {
            float xr[TM], wr[TN];
#pragma unroll
            for (int i = 0; i < TM; i++) xr[i] = sXT[k][ty + 16 * i];
#pragma unroll
            for (int j = 0; j < TN; j++) wr[j] = sW[(k0 + k) * FOUT + tx + 16 * j];
#pragma unroll
            for (int i = 0; i < TM; i++)
#pragma unroll
                for (int j = 0; j < TN; j++)
                    acc[i][j] += xr[i] * wr[j];
        }
    }
#pragma unroll
    for (int i = 0; i < TM; i++) {
        int gr = row0 + ty + 16 * i;
        if (gr < N) {
#pragma unroll
            for (int j = 0; j < TN; j++)
                out[(size_t)gr * FOUT + tx + 16 * j] = acc[i][j];
        }
    }
}

__global__ void k_gemm1(const float* __restrict__ X, const float* __restrict__ W, int N) {
    gemm_body<128, 64, 4, false>(X, W, g_xw1, N);
}
__global__ void k_gemm2(const float* __restrict__ W, int N) {
    gemm_body<64, 32, 2, false>(g_h1, W, g_xw2, N);
}
// layer-3 GEMM reads raw emb and applies tanh while staging into smem
__global__ void k_gemm3(const float* __restrict__ emb, const float* __restrict__ W, int N) {
    gemm_body<32, 16, 1, true>(emb, W, g_xw3, N);
}

// ---------------- CSR gather aggregation, one warp per node, 4x unroll ------
__global__ void k_agg1(const float* __restrict__ b, int N) {
    int node = (blockIdx.x * blockDim.x + threadIdx.x) >> 5;
    if (node >= N) return;
    int lane = threadIdx.x & 31;
    int beg = g_ptr[node], end = g_ptr[node + 1];
    float a0 = 0.0f, a1 = 0.0f;
    int p = beg;
    for (; p + 4 <= end; p += 4) {
        int2 e0 = g_edge[p], e1 = g_edge[p + 1], e2 = g_edge[p + 2], e3 = g_edge[p + 3];
        const float* s0 = g_xw1 + (size_t)e0.x * 64;
        const float* s1 = g_xw1 + (size_t)e1.x * 64;
        const float* s2 = g_xw1 + (size_t)e2.x * 64;
        const float* s3 = g_xw1 + (size_t)e3.x * 64;
        float n0 = __int_as_float(e0.y), n1 = __int_as_float(e1.y);
        float n2 = __int_as_float(e2.y), n3 = __int_as_float(e3.y);
        float v0a = s0[lane], v0b = s0[lane + 32];
        float v1a = s1[lane], v1b = s1[lane + 32];
        float v2a = s2[lane], v2b = s2[lane + 32];
        float v3a = s3[lane], v3b = s3[lane + 32];
        a0 += n0 * v0a; a1 += n0 * v0b;
        a0 += n1 * v1a; a1 += n1 * v1b;
        a0 += n2 * v2a; a1 += n2 * v2b;
        a0 += n3 * v3a; a1 += n3 * v3b;
    }
    for (; p < end; p++) {
        int2 e = g_edge[p];
        const float* s = g_xw1 + (size_t)e.x * 64;
        float nm = __int_as_float(e.y);
        a0 += nm * s[lane];
        a1 += nm * s[lane + 32];
    }
    float di = g_dinv[node];
    float d2 = di * di;
    const float* self = g_xw1 + (size_t)node * 64;
    a0 += d2 * self[lane]      + b[lane];
    a1 += d2 * self[lane + 32] + b[lane + 32];
    g_h1[(size_t)node * 64 + lane]      = tanhf(a0);
    g_h1[(size_t)node * 64 + lane + 32] = tanhf(a1);
}

__global__ void k_agg2(const float* __restrict__ b, float* __restrict__ emb, int N) {
    int node = (blockIdx.x * blockDim.x + threadIdx.x) >> 5;
    if (node >= N) return;
    int lane = threadIdx.x & 31;
    int beg = g_ptr[node], end = g_ptr[node + 1];
    float a = 0.0f;
    int p = beg;
    for (; p + 4 <= end; p += 4) {
        int2 e0 = g_edge[p], e1 = g_edge[p + 1], e2 = g_edge[p + 2], e3 = g_edge[p + 3];
        float v0 = g_xw2[(size_t)e0.x * 32 + lane];
        float v1 = g_xw2[(size_t)e1.x * 32 + lane];
        float v2 = g_xw2[(size_t)e2.x * 32 + lane];
        float v3 = g_xw2[(size_t)e3.x * 32 + lane];
        a += __int_as_float(e0.y) * v0;
        a += __int_as_float(e1.y) * v1;
        a += __int_as_float(e2.y) * v2;
        a += __int_as_float(e3.y) * v3;
    }
    for (; p < end; p++) {
        int2 e = g_edge[p];
        a += __int_as_float(e.y) * g_xw2[(size_t)e.x * 32 + lane];
    }
    float di = g_dinv[node];
    float val = a + di * di * g_xw2[(size_t)node * 32 + lane] + b[lane];
    emb[(size_t)node * 32 + lane] = val;
}

__global__ void k_agg3(const float* __restrict__ b, float* __restrict__ logits, int N) {
    int node = (blockIdx.x * blockDim.x + threadIdx.x) >> 5;
    if (node >= N) return;
    int lane = threadIdx.x & 31;
    int sub = lane >> 4;
    int f = lane & 15;
    int beg = g_ptr[node], end = g_ptr[node + 1];
    float a = 0.0f;
    int p = beg + sub;
    for (; p + 8 <= end; p += 8) {
        int2 e0 = g_edge[p],     e1 = g_edge[p + 2];
        int2 e2 = g_edge[p + 4], e3 = g_edge[p + 6];
        float v0 = g_xw3[(size_t)e0.x * 16 + f];
        float v1 = g_xw3[(size_t)e1.x * 16 + f];
        float v2 = g_xw3[(size_t)e2.x * 16 + f];
        float v3 = g_xw3[(size_t)e3.x * 16 + f];
        a += __int_as_float(e0.y) * v0;
        a += __int_as_float(e1.y) * v1;
        a += __int_as_float(e2.y) * v2;
        a += __int_as_float(e3.y) * v3;
    }
    for (; p < end; p += 2) {
        int2 e = g_edge[p];
        a += __int_as_float(e.y) * g_xw3[(size_t)e.x * 16 + f];
    }
    a += __shfl_xor_sync(0xffffffffu, a, 16);
    if (sub == 0) {
        float di = g_dinv[node];
        logits[(size_t)node * 16 + f] =
            a + di * di * g_xw3[(size_t)node * 16 + f] + b[f];
    }
}

// ---------------- launch: fork-join (CSR build || GEMM1) --------------------
extern "C" void kernel_launch(void* const* d_in, const int* in_sizes, int n_in,
                              void* d_out, int out_size) {
    const float* x  = (const float*)d_in[0];
    const int*   ei = (const int*)d_in[1];
    const float* ew = (const float*)d_in[2];
    const float* W1 = (const float*)d_in[3];
    const float* b1 = (const float*)d_in[4];
    const float* W2 = (const float*)d_in[5];
    const float* b2 = (const float*)d_in[6];
    const float* W3 = (const float*)d_in[7];
    const float* b3 = (const float*)d_in[8];

    const int N = in_sizes[0] / 128;
    const int E = in_sizes[2];

    float* logits = (float*)d_out;                    // [N,16]
    float* emb    = (float*)d_out + (size_t)N * 16;   // [N,32]

    const int T = 256;
    auto cdiv = [](long long a, long long b) { return (int)((a + b - 1) / b); };
    const int warpGrid = cdiv((long long)N * 32, T);
    const int nb = cdiv(N, SCAN_T);

    // lazily-created aux stream + events (created on the non-capture
    // correctness call; reused by the capture call — deterministic work)
    static cudaStream_t s_aux = nullptr;
    static cudaEvent_t ev_fork = nullptr, ev_join = nullptr;
    if (s_aux == nullptr) {
        cudaStreamCreate(&s_aux);
        cudaEventCreateWithFlags(&ev_fork, cudaEventDisableTiming);
        cudaEventCreateWithFlags(&ev_join, cudaEventDisableTiming);
    }

    // ---- fork: CSR build on aux stream ----
    cudaEventRecord(ev_fork, 0);
    cudaStreamWaitEvent(s_aux, ev_fork, 0);
    k_init <<<cdiv(N, T), T, 0, s_aux>>>(ei, N);
    k_cnt  <<<cdiv(E, T), T, 0, s_aux>>>(ei, ew, E, N);
    k_scan1<<<nb, SCAN_T, 0, s_aux>>>(N);
    k_scan2<<<1, 128,    0, s_aux>>>(nb);
    k_scan3<<<nb, SCAN_T, 0, s_aux>>>(N, E);
    k_fill <<<cdiv(E, T), T, 0, s_aux>>>(ei, ew, E, N);
    cudaEventRecord(ev_join, s_aux);

    // ---- concurrent on main stream: layer-1 GEMM ----
    k_gemm1<<<cdiv(N, 128), T>>>(x, W1, N);

    // ---- join, then the dependent chain ----
    cudaStreamWaitEvent(0, ev_join, 0);
    k_agg1 <<<warpGrid, T>>>(b1, N);
    k_gemm2<<<cdiv(N, 128), T>>>(W2, N);
    k_agg2 <<<warpGrid, T>>>(b2, emb, N);
    k_gemm3<<<cdiv(N, 128), T>>>(emb, W3, N);
    k_agg3 <<<warpGrid, T>>>(b3, logits, N);
}